// round 1
// baseline (speedup 1.0000x reference)
#include <cuda_runtime.h>
#include <cuda_bf16.h>
#include <cstdint>

// Problem constants
#define BATCH   16
#define CDIM    512
#define LIN     1024
#define KW      3
#define LP      1022      // LIN - KW + 1
#define HEADS   8
#define DH      64        // CDIM / HEADS
#define SCALE   0.04419417382415922f   // 1/sqrt(512)

// q/k/v scratch: 16*512*1022 floats each = 33.5 MB
#define QKV_ELEMS (BATCH * CDIM * LP)
__device__ float g_q[QKV_ELEMS];
__device__ float g_k[QKV_ELEMS];
__device__ float g_v[QKV_ELEMS];

// ---------------------------------------------------------------------------
// Conv1d as implicit GEMM:
//   out[b, o, l] = bias[o] + sum_{i,k} x[b, i, l+k] * w[o, i, k]
// Tile: 64 (o) x 64 (l) per block, K-loop over channels in chunks of 16.
// 256 threads, each computes a 4x4 microtile.
// Grid: (8 o-tiles, 16 l-tiles, 16 batches)
// ---------------------------------------------------------------------------
__global__ __launch_bounds__(256, 4)
void conv1d_gemm_kernel(const float* __restrict__ x,
                        const float* __restrict__ w,
                        const float* __restrict__ bias,
                        float* __restrict__ out)
{
    const int otile = blockIdx.x * 64;
    const int ltile = blockIdx.y * 64;
    const int b     = blockIdx.z;

    __shared__ float xs[16][68];        // 16 channels x 66 (+pad) input samples
    __shared__ float ws[16][3][64];     // [i][k][o]

    const int tid = threadIdx.x;
    const int tx  = tid & 15;           // l group
    const int ty  = tid >> 4;           // o group
    const int tx4 = tx * 4;
    const int ty4 = ty * 4;

    float acc[4][4];
    #pragma unroll
    for (int a = 0; a < 4; a++)
        #pragma unroll
        for (int c = 0; c < 4; c++) acc[a][c] = 0.f;

    const float* xb = x + (size_t)b * CDIM * LIN;

    for (int i0 = 0; i0 < CDIM; i0 += 16) {
        // load x tile: rows i0..i0+15, cols ltile..ltile+65
        for (int t = tid; t < 16 * 66; t += 256) {
            int r = t / 66, c = t % 66;
            int l = ltile + c;
            xs[r][c] = (l < LIN) ? xb[(size_t)(i0 + r) * LIN + l] : 0.f;
        }
        // load w tile: w[(otile+o)*1536 + (i0+i)*3 + k] -> ws[i][k][o]
        for (int t = tid; t < 64 * 48; t += 256) {
            int o = t / 48, rem = t % 48;
            int i = rem / 3, k = rem % 3;
            ws[i][k][o] = w[(size_t)(otile + o) * (CDIM * KW) + (i0 + i) * KW + k];
        }
        __syncthreads();

        #pragma unroll
        for (int i = 0; i < 16; i++) {
            float xv[6];
            const float4 a4 = *(const float4*)&xs[i][tx4];
            xv[0] = a4.x; xv[1] = a4.y; xv[2] = a4.z; xv[3] = a4.w;
            xv[4] = xs[i][tx4 + 4];
            xv[5] = xs[i][tx4 + 5];
            #pragma unroll
            for (int k = 0; k < 3; k++) {
                const float4 w4 = *(const float4*)&ws[i][k][ty4];
                const float wv[4] = {w4.x, w4.y, w4.z, w4.w};
                #pragma unroll
                for (int oi = 0; oi < 4; oi++)
                    #pragma unroll
                    for (int li = 0; li < 4; li++)
                        acc[oi][li] += wv[oi] * xv[li + k];
            }
        }
        __syncthreads();
    }

    // epilogue: add bias, store (row stride 1022 -> scalar stores, guarded)
    #pragma unroll
    for (int oi = 0; oi < 4; oi++) {
        const int o = otile + ty4 + oi;
        const float bo = bias[o];
        float* orow = out + ((size_t)b * CDIM + o) * LP;
        #pragma unroll
        for (int li = 0; li < 4; li++) {
            const int l = ltile + tx4 + li;
            if (l < LP) orow[l] = acc[oi][li] + bo;
        }
    }
}

// ---------------------------------------------------------------------------
// Flash attention per (query-tile, head, batch).
// Tiles of 64 queries x 64 keys, Dh = 64. Online softmax.
// Grid: (16 q-tiles, 8 heads, 16 batches), 256 threads.
// Dynamic smem layout (floats):
//   Qs[64][64]  (d-major)      4096
//   Ks[64][64]  (d-major)      4096
//   Vs[64][68]  (k-major,pad)  4352
//   Ss[64][68]  (q-major,pad)  4352
//   mrow[64], lrow[64], arow[64]
// ---------------------------------------------------------------------------
#define ATTN_SMEM_FLOATS (4096 + 4096 + 4352 + 4352 + 192)
#define ATTN_SMEM_BYTES  (ATTN_SMEM_FLOATS * 4)

__global__ __launch_bounds__(256, 1)
void flash_attn_kernel(const float* __restrict__ gq,
                       const float* __restrict__ gk,
                       const float* __restrict__ gv,
                       float* __restrict__ out)
{
    extern __shared__ float sm[];
    float* Qs   = sm;                 // [d*64 + q]
    float* Ks   = Qs + 4096;          // [d*64 + k]
    float* Vs   = Ks + 4096;          // [k*68 + d]
    float* Ss   = Vs + 4352;          // [q*68 + k]
    float* mrow = Ss + 4352;
    float* lrow = mrow + 64;
    float* arow = lrow + 64;

    const int qbase = blockIdx.x * 64;
    const int h     = blockIdx.y;
    const int b     = blockIdx.z;
    const int tid   = threadIdx.x;
    const int tx    = tid & 15;
    const int ty    = tid >> 4;

    const size_t chan0 = ((size_t)b * CDIM + h * DH) * LP;
    const float* qg = gq + chan0;
    const float* kg = gk + chan0;
    const float* vg = gv + chan0;

    // Load Q tile: Qs[d][q]
    for (int t = tid; t < 64 * 64; t += 256) {
        const int d = t >> 6, q2 = t & 63;
        const int lq = qbase + q2;
        Qs[d * 64 + q2] = (lq < LP) ? qg[(size_t)d * LP + lq] : 0.f;
    }
    if (tid < 64) { mrow[tid] = -1e30f; lrow[tid] = 0.f; }

    float acc[4][4];
    #pragma unroll
    for (int a = 0; a < 4; a++)
        #pragma unroll
        for (int c = 0; c < 4; c++) acc[a][c] = 0.f;

    for (int kt = 0; kt < 16; kt++) {
        const int kbase = kt * 64;
        const int klen  = min(64, LP - kbase);
        __syncthreads();   // protect Ks/Vs/Ss from previous iteration readers

        // Load K tile Ks[d][k] and V tile Vs[k][d]
        for (int t = tid; t < 64 * 64; t += 256) {
            const int d = t >> 6, kk = t & 63;
            const int lk = kbase + kk;
            const float kvv = (lk < LP) ? kg[(size_t)d * LP + lk] : 0.f;
            const float vvv = (lk < LP) ? vg[(size_t)d * LP + lk] : 0.f;
            Ks[d * 64 + kk] = kvv;
            Vs[kk * 68 + d] = vvv;
        }
        __syncthreads();

        // S = scale * Q^T K : thread covers q = ty*4..+3, k = tx*4..+3
        {
            float s[4][4];
            #pragma unroll
            for (int a = 0; a < 4; a++)
                #pragma unroll
                for (int c = 0; c < 4; c++) s[a][c] = 0.f;
            #pragma unroll 8
            for (int d = 0; d < 64; d++) {
                const float4 q4 = *(const float4*)&Qs[d * 64 + ty * 4];
                const float4 k4 = *(const float4*)&Ks[d * 64 + tx * 4];
                const float qv[4] = {q4.x, q4.y, q4.z, q4.w};
                const float kv[4] = {k4.x, k4.y, k4.z, k4.w};
                #pragma unroll
                for (int qi = 0; qi < 4; qi++)
                    #pragma unroll
                    for (int ki = 0; ki < 4; ki++)
                        s[qi][ki] += qv[qi] * kv[ki];
            }
            #pragma unroll
            for (int qi = 0; qi < 4; qi++) {
                float4 o4;
                o4.x = s[qi][0] * SCALE;
                o4.y = s[qi][1] * SCALE;
                o4.z = s[qi][2] * SCALE;
                o4.w = s[qi][3] * SCALE;
                *(float4*)&Ss[(ty * 4 + qi) * 68 + tx * 4] = o4;
            }
        }
        __syncthreads();

        // Row-wise online softmax: one thread per query row
        if (tid < 64) {
            const int q2 = tid;
            float* srow = &Ss[q2 * 68];
            const float mold = mrow[q2];
            float mx = mold;
            for (int kk = 0; kk < klen; kk++) mx = fmaxf(mx, srow[kk]);
            const float alpha = __expf(mold - mx);
            float ps = 0.f;
            for (int kk = 0; kk < klen; kk++) {
                const float p = __expf(srow[kk] - mx);
                srow[kk] = p;
                ps += p;
            }
            for (int kk = klen; kk < 64; kk++) srow[kk] = 0.f;
            mrow[q2] = mx;
            lrow[q2] = lrow[q2] * alpha + ps;
            arow[q2] = alpha;
        }
        __syncthreads();

        // O = O*alpha + P V : thread covers q = tx + 16*qi, d = ty*4 + di
        {
            float al[4];
            #pragma unroll
            for (int qi = 0; qi < 4; qi++) al[qi] = arow[tx + 16 * qi];
            #pragma unroll
            for (int qi = 0; qi < 4; qi++)
                #pragma unroll
                for (int di = 0; di < 4; di++) acc[qi][di] *= al[qi];

            #pragma unroll 4
            for (int kk = 0; kk < 64; kk++) {
                const float4 v4 = *(const float4*)&Vs[kk * 68 + ty * 4];
                const float vv[4] = {v4.x, v4.y, v4.z, v4.w};
                float p[4];
                #pragma unroll
                for (int qi = 0; qi < 4; qi++) p[qi] = Ss[(tx + 16 * qi) * 68 + kk];
                #pragma unroll
                for (int qi = 0; qi < 4; qi++)
                    #pragma unroll
                    for (int di = 0; di < 4; di++)
                        acc[qi][di] += p[qi] * vv[di];
            }
        }
    }

    // Epilogue: divide by lsum, write out[b, h*64+d, lq]
    float il[4];
    #pragma unroll
    for (int qi = 0; qi < 4; qi++) il[qi] = 1.f / lrow[tx + 16 * qi];

    #pragma unroll
    for (int di = 0; di < 4; di++) {
        float* orow = out + ((size_t)b * CDIM + h * DH + ty * 4 + di) * LP;
        #pragma unroll
        for (int qi = 0; qi < 4; qi++) {
            const int lq = qbase + tx + 16 * qi;
            if (lq < LP) orow[lq] = acc[qi][di] * il[qi];
        }
    }
}

// ---------------------------------------------------------------------------
extern "C" void kernel_launch(void* const* d_in, const int* in_sizes, int n_in,
                              void* d_out, int out_size)
{
    const float* x  = (const float*)d_in[0];
    const float* w0 = (const float*)d_in[1];
    const float* b0 = (const float*)d_in[2];
    const float* w1 = (const float*)d_in[3];
    const float* b1 = (const float*)d_in[4];
    const float* w2 = (const float*)d_in[5];
    const float* b2 = (const float*)d_in[6];
    float* out = (float*)d_out;

    float *pq, *pk, *pv;
    cudaGetSymbolAddress((void**)&pq, g_q);
    cudaGetSymbolAddress((void**)&pk, g_k);
    cudaGetSymbolAddress((void**)&pv, g_v);

    dim3 cgrid(CDIM / 64, 16, BATCH);
    conv1d_gemm_kernel<<<cgrid, 256>>>(x, w0, b0, pq);
    conv1d_gemm_kernel<<<cgrid, 256>>>(x, w1, b1, pk);
    conv1d_gemm_kernel<<<cgrid, 256>>>(x, w2, b2, pv);

    cudaFuncSetAttribute(flash_attn_kernel,
                         cudaFuncAttributeMaxDynamicSharedMemorySize,
                         ATTN_SMEM_BYTES);
    dim3 agrid(16, HEADS, BATCH);
    flash_attn_kernel<<<agrid, 256, ATTN_SMEM_BYTES>>>(pq, pk, pv, out);
}

// round 2
// speedup vs baseline: 1.9214x; 1.9214x over previous
#include <cuda_runtime.h>
#include <cuda_bf16.h>
#include <cstdint>

// Problem constants
#define BATCH   16
#define CDIM    512
#define LIN     1024
#define KW      3
#define LP      1022      // LIN - KW + 1
#define HEADS   8
#define DH      64        // CDIM / HEADS
#define SCALE   0.04419417382415922f   // 1/sqrt(512)

// q/k/v scratch: 16*512*1022 floats each = 33.5 MB
#define QKV_ELEMS (BATCH * CDIM * LP)
__device__ float g_q[QKV_ELEMS];
__device__ float g_k[QKV_ELEMS];
__device__ float g_v[QKV_ELEMS];

// ---------------------------------------------------------------------------
// tf32 helpers
// ---------------------------------------------------------------------------
__device__ __forceinline__ uint32_t f2tf32(float f) {
    uint32_t r;
    asm("cvt.rna.tf32.f32 %0, %1;" : "=r"(r) : "f"(f));
    return r;
}

__device__ __forceinline__ void mma_tf32(float c[4], const uint32_t a[4],
                                         uint32_t b0, uint32_t b1) {
    asm volatile(
        "mma.sync.aligned.m16n8k8.row.col.f32.tf32.tf32.f32 "
        "{%0,%1,%2,%3},{%4,%5,%6,%7},{%8,%9},{%0,%1,%2,%3};"
        : "+f"(c[0]), "+f"(c[1]), "+f"(c[2]), "+f"(c[3])
        : "r"(a[0]), "r"(a[1]), "r"(a[2]), "r"(a[3]), "r"(b0), "r"(b1));
}

// ---------------------------------------------------------------------------
// Fused tf32 tensor-core conv1d (all 3 convs in one launch).
//   out[b, o, l] = bias[o] + sum_{i,k} x[b, i, l+k] * w[o, i, k]
// GEMM view per (b, conv): Out[512, 1022] = W[512, 1536] @ Xcol[1536, 1022],
//   Xcol[i*3+k][l] = x[b, i, l+k]   (implicit im2col in smem)
// Block tile: 128 (o) x 128 (l). K-chunks of 8 channels = 24 k' values.
// 8 warps in 4(m) x 2(n) grid; each warp computes 32(o) x 64(l) with
// m16n8k8 tf32 mma (2 m-iters x 8 n-iters per 8-wide k-step).
// Grid: (8 l-tiles, 4 o-tiles, 48 = batch*3)
// ---------------------------------------------------------------------------
#define BM 128
#define BN 128
#define BKCH 8
#define BK 24            // BKCH * 3
#define WS_STRIDE 28     // (m*28+k)%32 = (4m+k)%32 -> conflict-free frag reads
#define XS_STRIDE 132    // BN+4; (r*132+c)%32 = (4r+c)%32 -> conflict-free

__global__ __launch_bounds__(256, 2)
void conv_tf32_kernel(const float* __restrict__ x,
                      const float* __restrict__ w0, const float* __restrict__ bb0,
                      const float* __restrict__ w1, const float* __restrict__ bb1,
                      const float* __restrict__ w2, const float* __restrict__ bb2,
                      float* __restrict__ oq, float* __restrict__ ok,
                      float* __restrict__ ov)
{
    const int cid = blockIdx.z % 3;
    const int b   = blockIdx.z / 3;
    const float* w    = (cid == 0) ? w0  : (cid == 1) ? w1  : w2;
    const float* bias = (cid == 0) ? bb0 : (cid == 1) ? bb1 : bb2;
    float*       out  = (cid == 0) ? oq  : (cid == 1) ? ok  : ov;

    const int ltile = blockIdx.x * BN;
    const int otile = blockIdx.y * BM;

    __shared__ uint32_t ws[BM][WS_STRIDE];   // A tile: [o][k']  (tf32)
    __shared__ uint32_t xs[BK][XS_STRIDE];   // B tile: [k'][l]  (tf32, im2col)

    const int tid  = threadIdx.x;
    const int lane = tid & 31;
    const int warp = tid >> 5;
    const int wm   = warp & 3;       // 0..3 -> m offset wm*32
    const int wn   = warp >> 2;      // 0..1 -> n offset wn*64
    const int g    = lane >> 2;      // group (0..7)
    const int tg   = lane & 3;       // thread-in-group (0..3)

    float c[2][8][4];
    #pragma unroll
    for (int mi = 0; mi < 2; mi++)
        #pragma unroll
        for (int ni = 0; ni < 8; ni++)
            #pragma unroll
            for (int r = 0; r < 4; r++) c[mi][ni][r] = 0.f;

    const float* xb = x + (size_t)b * CDIM * LIN;

    for (int ch0 = 0; ch0 < CDIM; ch0 += BKCH) {
        __syncthreads();
        // --- load W tile: rows o=0..127, cols k' = ch0*3 .. +23 (contiguous) ---
        // 128 rows * 6 float4 = 768 float4 loads
        for (int t = tid; t < 128 * 6; t += 256) {
            const int o = t / 6, seg = t % 6;
            const float4 wv = *(const float4*)&w[(size_t)(otile + o) * (CDIM * KW)
                                                 + ch0 * KW + seg * 4];
            uint32_t* dst = &ws[o][seg * 4];
            dst[0] = f2tf32(wv.x); dst[1] = f2tf32(wv.y);
            dst[2] = f2tf32(wv.z); dst[3] = f2tf32(wv.w);
        }
        // --- im2col X tile: 8 channels, positions ltile..ltile+129 ---
        for (int t = tid; t < BKCH * 130; t += 256) {
            const int ch = t / 130, p = t % 130;
            const int gl = ltile + p;
            const float v = (gl < LIN) ? xb[(size_t)(ch0 + ch) * LIN + gl] : 0.f;
            const uint32_t tv = f2tf32(v);
            const int rbase = ch * 3;
            #pragma unroll
            for (int tap = 0; tap < 3; tap++) {
                const int col = p - tap;
                if (col >= 0 && col < BN) xs[rbase + tap][col] = tv;
            }
        }
        __syncthreads();

        #pragma unroll
        for (int kk = 0; kk < BK; kk += 8) {
            uint32_t a[2][4];
            #pragma unroll
            for (int mi = 0; mi < 2; mi++) {
                const int row = wm * 32 + mi * 16;
                a[mi][0] = ws[row + g    ][kk + tg    ];
                a[mi][1] = ws[row + g + 8][kk + tg    ];
                a[mi][2] = ws[row + g    ][kk + tg + 4];
                a[mi][3] = ws[row + g + 8][kk + tg + 4];
            }
            #pragma unroll
            for (int ni = 0; ni < 8; ni++) {
                const int coln = wn * 64 + ni * 8 + g;
                const uint32_t b0 = xs[kk + tg    ][coln];
                const uint32_t b1 = xs[kk + tg + 4][coln];
                mma_tf32(c[0][ni], a[0], b0, b1);
                mma_tf32(c[1][ni], a[1], b0, b1);
            }
        }
    }

    // --- epilogue: bias + store (float2, cols 2tg/2tg+1 contiguous) ---
    #pragma unroll
    for (int mi = 0; mi < 2; mi++) {
        const int r0 = otile + wm * 32 + mi * 16 + g;
        const int r1 = r0 + 8;
        const float bv0 = bias[r0];
        const float bv1 = bias[r1];
        float* row0 = out + ((size_t)b * CDIM + r0) * LP;
        float* row1 = out + ((size_t)b * CDIM + r1) * LP;
        #pragma unroll
        for (int ni = 0; ni < 8; ni++) {
            const int l0 = ltile + wn * 64 + ni * 8 + tg * 2;
            if (l0 < LP) {
                *(float2*)&row0[l0] = make_float2(c[mi][ni][0] + bv0,
                                                  c[mi][ni][1] + bv0);
                *(float2*)&row1[l0] = make_float2(c[mi][ni][2] + bv1,
                                                  c[mi][ni][3] + bv1);
            }
        }
    }
}

// ---------------------------------------------------------------------------
// Flash attention (unchanged from R0 baseline).
// ---------------------------------------------------------------------------
#define ATTN_SMEM_FLOATS (4096 + 4096 + 4352 + 4352 + 192)
#define ATTN_SMEM_BYTES  (ATTN_SMEM_FLOATS * 4)

__global__ __launch_bounds__(256, 1)
void flash_attn_kernel(const float* __restrict__ gq,
                       const float* __restrict__ gk,
                       const float* __restrict__ gv,
                       float* __restrict__ out)
{
    extern __shared__ float sm[];
    float* Qs   = sm;                 // [d*64 + q]
    float* Ks   = Qs + 4096;          // [d*64 + k]
    float* Vs   = Ks + 4096;          // [k*68 + d]
    float* Ss   = Vs + 4352;          // [q*68 + k]
    float* mrow = Ss + 4352;
    float* lrow = mrow + 64;
    float* arow = lrow + 64;

    const int qbase = blockIdx.x * 64;
    const int h     = blockIdx.y;
    const int b     = blockIdx.z;
    const int tid   = threadIdx.x;
    const int tx    = tid & 15;
    const int ty    = tid >> 4;

    const size_t chan0 = ((size_t)b * CDIM + h * DH) * LP;
    const float* qg = gq + chan0;
    const float* kg = gk + chan0;
    const float* vg = gv + chan0;

    for (int t = tid; t < 64 * 64; t += 256) {
        const int d = t >> 6, q2 = t & 63;
        const int lq = qbase + q2;
        Qs[d * 64 + q2] = (lq < LP) ? qg[(size_t)d * LP + lq] : 0.f;
    }
    if (tid < 64) { mrow[tid] = -1e30f; lrow[tid] = 0.f; }

    float acc[4][4];
    #pragma unroll
    for (int a = 0; a < 4; a++)
        #pragma unroll
        for (int cc = 0; cc < 4; cc++) acc[a][cc] = 0.f;

    for (int kt = 0; kt < 16; kt++) {
        const int kbase = kt * 64;
        const int klen  = min(64, LP - kbase);
        __syncthreads();

        for (int t = tid; t < 64 * 64; t += 256) {
            const int d = t >> 6, kk = t & 63;
            const int lk = kbase + kk;
            const float kvv = (lk < LP) ? kg[(size_t)d * LP + lk] : 0.f;
            const float vvv = (lk < LP) ? vg[(size_t)d * LP + lk] : 0.f;
            Ks[d * 64 + kk] = kvv;
            Vs[kk * 68 + d] = vvv;
        }
        __syncthreads();

        {
            float s[4][4];
            #pragma unroll
            for (int a = 0; a < 4; a++)
                #pragma unroll
                for (int cc = 0; cc < 4; cc++) s[a][cc] = 0.f;
            #pragma unroll 8
            for (int d = 0; d < 64; d++) {
                const float4 q4 = *(const float4*)&Qs[d * 64 + ty * 4];
                const float4 k4 = *(const float4*)&Ks[d * 64 + tx * 4];
                const float qv[4] = {q4.x, q4.y, q4.z, q4.w};
                const float kv[4] = {k4.x, k4.y, k4.z, k4.w};
                #pragma unroll
                for (int qi = 0; qi < 4; qi++)
                    #pragma unroll
                    for (int ki = 0; ki < 4; ki++)
                        s[qi][ki] += qv[qi] * kv[ki];
            }
            #pragma unroll
            for (int qi = 0; qi < 4; qi++) {
                float4 o4;
                o4.x = s[qi][0] * SCALE;
                o4.y = s[qi][1] * SCALE;
                o4.z = s[qi][2] * SCALE;
                o4.w = s[qi][3] * SCALE;
                *(float4*)&Ss[(ty * 4 + qi) * 68 + tx * 4] = o4;
            }
        }
        __syncthreads();

        if (tid < 64) {
            const int q2 = tid;
            float* srow = &Ss[q2 * 68];
            const float mold = mrow[q2];
            float mx = mold;
            for (int kk = 0; kk < klen; kk++) mx = fmaxf(mx, srow[kk]);
            const float alpha = __expf(mold - mx);
            float ps = 0.f;
            for (int kk = 0; kk < klen; kk++) {
                const float p = __expf(srow[kk] - mx);
                srow[kk] = p;
                ps += p;
            }
            for (int kk = klen; kk < 64; kk++) srow[kk] = 0.f;
            mrow[q2] = mx;
            lrow[q2] = lrow[q2] * alpha + ps;
            arow[q2] = alpha;
        }
        __syncthreads();

        {
            float al[4];
            #pragma unroll
            for (int qi = 0; qi < 4; qi++) al[qi] = arow[tx + 16 * qi];
            #pragma unroll
            for (int qi = 0; qi < 4; qi++)
                #pragma unroll
                for (int di = 0; di < 4; di++) acc[qi][di] *= al[qi];

            #pragma unroll 4
            for (int kk = 0; kk < 64; kk++) {
                const float4 v4 = *(const float4*)&Vs[kk * 68 + ty * 4];
                const float vv[4] = {v4.x, v4.y, v4.z, v4.w};
                float p[4];
                #pragma unroll
                for (int qi = 0; qi < 4; qi++) p[qi] = Ss[(tx + 16 * qi) * 68 + kk];
                #pragma unroll
                for (int qi = 0; qi < 4; qi++)
                    #pragma unroll
                    for (int di = 0; di < 4; di++)
                        acc[qi][di] += p[qi] * vv[di];
            }
        }
    }

    float il[4];
    #pragma unroll
    for (int qi = 0; qi < 4; qi++) il[qi] = 1.f / lrow[tx + 16 * qi];

    #pragma unroll
    for (int di = 0; di < 4; di++) {
        float* orow = out + ((size_t)b * CDIM + h * DH + ty * 4 + di) * LP;
        #pragma unroll
        for (int qi = 0; qi < 4; qi++) {
            const int lq = qbase + tx + 16 * qi;
            if (lq < LP) orow[lq] = acc[qi][di] * il[qi];
        }
    }
}

// ---------------------------------------------------------------------------
extern "C" void kernel_launch(void* const* d_in, const int* in_sizes, int n_in,
                              void* d_out, int out_size)
{
    const float* x  = (const float*)d_in[0];
    const float* w0 = (const float*)d_in[1];
    const float* b0 = (const float*)d_in[2];
    const float* w1 = (const float*)d_in[3];
    const float* b1 = (const float*)d_in[4];
    const float* w2 = (const float*)d_in[5];
    const float* b2 = (const float*)d_in[6];
    float* out = (float*)d_out;

    float *pq, *pk, *pv;
    cudaGetSymbolAddress((void**)&pq, g_q);
    cudaGetSymbolAddress((void**)&pk, g_k);
    cudaGetSymbolAddress((void**)&pv, g_v);

    dim3 cgrid(8, 4, BATCH * 3);
    conv_tf32_kernel<<<cgrid, 256>>>(x, w0, b0, w1, b1, w2, b2, pq, pk, pv);

    cudaFuncSetAttribute(flash_attn_kernel,
                         cudaFuncAttributeMaxDynamicSharedMemorySize,
                         ATTN_SMEM_BYTES);
    dim3 agrid(16, HEADS, BATCH);
    flash_attn_kernel<<<agrid, 256, ATTN_SMEM_BYTES>>>(pq, pk, pv, out);
}

// round 4
// speedup vs baseline: 3.0625x; 1.5939x over previous
#include <cuda_runtime.h>
#include <cuda_bf16.h>
#include <cstdint>

// Problem constants
#define BATCH   16
#define CDIM    512
#define LIN     1024
#define KW      3
#define LP      1022      // LIN - KW + 1
#define LPAD    1024      // padded scratch row stride (16B-aligned rows)
#define HEADS   8
#define DH      64        // CDIM / HEADS
#define SCALE   0.04419417382415922f   // 1/sqrt(512)

// q/k/v scratch: 16*512*1024 floats each = 33.55 MB
#define QKV_ELEMS (BATCH * CDIM * LPAD)
__device__ float g_q[QKV_ELEMS];
__device__ float g_k[QKV_ELEMS];
__device__ float g_v[QKV_ELEMS];

// ---------------------------------------------------------------------------
// tf32 helpers
// ---------------------------------------------------------------------------
__device__ __forceinline__ uint32_t f2tf32(float f) {
    uint32_t r;
    asm("cvt.rna.tf32.f32 %0, %1;" : "=r"(r) : "f"(f));
    return r;
}

__device__ __forceinline__ void mma_tf32(float c[4], const uint32_t a[4],
                                         uint32_t b0, uint32_t b1) {
    asm volatile(
        "mma.sync.aligned.m16n8k8.row.col.f32.tf32.tf32.f32 "
        "{%0,%1,%2,%3},{%4,%5,%6,%7},{%8,%9},{%0,%1,%2,%3};"
        : "+f"(c[0]), "+f"(c[1]), "+f"(c[2]), "+f"(c[3])
        : "r"(a[0]), "r"(a[1]), "r"(a[2]), "r"(a[3]), "r"(b0), "r"(b1));
}

// ---------------------------------------------------------------------------
// Fused tf32 tensor-core conv1d. Writes to padded-stride scratch (LPAD),
// zero-filling pad columns so downstream vector loads read deterministic 0s.
// ---------------------------------------------------------------------------
#define BM 128
#define BN 128
#define BKCH 8
#define BK 24
#define WS_STRIDE 28
#define XS_STRIDE 132

__global__ __launch_bounds__(256, 2)
void conv_tf32_kernel(const float* __restrict__ x,
                      const float* __restrict__ w0, const float* __restrict__ bb0,
                      const float* __restrict__ w1, const float* __restrict__ bb1,
                      const float* __restrict__ w2, const float* __restrict__ bb2,
                      float* __restrict__ oq, float* __restrict__ ok,
                      float* __restrict__ ov)
{
    const int cid = blockIdx.z % 3;
    const int b   = blockIdx.z / 3;
    const float* w    = (cid == 0) ? w0  : (cid == 1) ? w1  : w2;
    const float* bias = (cid == 0) ? bb0 : (cid == 1) ? bb1 : bb2;
    float*       out  = (cid == 0) ? oq  : (cid == 1) ? ok  : ov;

    const int ltile = blockIdx.x * BN;
    const int otile = blockIdx.y * BM;

    __shared__ uint32_t ws[BM][WS_STRIDE];
    __shared__ uint32_t xs[BK][XS_STRIDE];

    const int tid  = threadIdx.x;
    const int lane = tid & 31;
    const int warp = tid >> 5;
    const int wm   = warp & 3;
    const int wn   = warp >> 2;
    const int g    = lane >> 2;
    const int tg   = lane & 3;

    float c[2][8][4];
    #pragma unroll
    for (int mi = 0; mi < 2; mi++)
        #pragma unroll
        for (int ni = 0; ni < 8; ni++)
            #pragma unroll
            for (int r = 0; r < 4; r++) c[mi][ni][r] = 0.f;

    const float* xb = x + (size_t)b * CDIM * LIN;

    for (int ch0 = 0; ch0 < CDIM; ch0 += BKCH) {
        __syncthreads();
        for (int t = tid; t < 128 * 6; t += 256) {
            const int o = t / 6, seg = t % 6;
            const float4 wv = *(const float4*)&w[(size_t)(otile + o) * (CDIM * KW)
                                                 + ch0 * KW + seg * 4];
            uint32_t* dst = &ws[o][seg * 4];
            dst[0] = f2tf32(wv.x); dst[1] = f2tf32(wv.y);
            dst[2] = f2tf32(wv.z); dst[3] = f2tf32(wv.w);
        }
        for (int t = tid; t < BKCH * 130; t += 256) {
            const int ch = t / 130, p = t % 130;
            const int gl = ltile + p;
            const float v = (gl < LIN) ? xb[(size_t)(ch0 + ch) * LIN + gl] : 0.f;
            const uint32_t tv = f2tf32(v);
            const int rbase = ch * 3;
            #pragma unroll
            for (int tap = 0; tap < 3; tap++) {
                const int col = p - tap;
                if (col >= 0 && col < BN) xs[rbase + tap][col] = tv;
            }
        }
        __syncthreads();

        #pragma unroll
        for (int kk = 0; kk < BK; kk += 8) {
            uint32_t a[2][4];
            #pragma unroll
            for (int mi = 0; mi < 2; mi++) {
                const int row = wm * 32 + mi * 16;
                a[mi][0] = ws[row + g    ][kk + tg    ];
                a[mi][1] = ws[row + g + 8][kk + tg    ];
                a[mi][2] = ws[row + g    ][kk + tg + 4];
                a[mi][3] = ws[row + g + 8][kk + tg + 4];
            }
            #pragma unroll
            for (int ni = 0; ni < 8; ni++) {
                const int coln = wn * 64 + ni * 8 + g;
                const uint32_t b0 = xs[kk + tg    ][coln];
                const uint32_t b1 = xs[kk + tg + 4][coln];
                mma_tf32(c[0][ni], a[0], b0, b1);
                mma_tf32(c[1][ni], a[1], b0, b1);
            }
        }
    }

    // epilogue: bias + store to padded-stride scratch; pad cols get zeros
    #pragma unroll
    for (int mi = 0; mi < 2; mi++) {
        const int r0 = otile + wm * 32 + mi * 16 + g;
        const int r1 = r0 + 8;
        const float bv0 = bias[r0];
        const float bv1 = bias[r1];
        float* row0 = out + ((size_t)b * CDIM + r0) * LPAD;
        float* row1 = out + ((size_t)b * CDIM + r1) * LPAD;
        #pragma unroll
        for (int ni = 0; ni < 8; ni++) {
            const int l0 = ltile + wn * 64 + ni * 8 + tg * 2;
            if (l0 < LP) {
                *(float2*)&row0[l0] = make_float2(c[mi][ni][0] + bv0,
                                                  c[mi][ni][1] + bv0);
                *(float2*)&row1[l0] = make_float2(c[mi][ni][2] + bv1,
                                                  c[mi][ni][3] + bv1);
            } else {
                *(float2*)&row0[l0] = make_float2(0.f, 0.f);
                *(float2*)&row1[l0] = make_float2(0.f, 0.f);
            }
        }
    }
}

// ---------------------------------------------------------------------------
// tf32 tensor-core flash attention (reads padded-stride scratch, LPAD=1024).
// Block: 128 queries x (b,h). 8 warps, each owns 16 query rows.
// k-tiles of 64 keys. Online softmax in registers (shfl across quad lanes).
// Smem (uint32 units, dynamic):
//   QPs [8704]: Q as [d=64][q=128] stride 136; aliased by P [q=128][k=64]
//               stride 68; finally by Ops(float) [d=64][q=128] stride 132.
//   Ks  [4608]: K tile [d=64][k=64] stride 72   (tf32)
//   Vs  [4352]: V tile [d=64][k=64] stride 68   (tf32)
// Total 17664 u32 = 70656 B -> 2 CTAs/SM.
// Grid: (8 q-tiles, 128 bh), 256 threads.
// ---------------------------------------------------------------------------
#define ATTN_SMEM_BYTES (17664 * 4)

__global__ __launch_bounds__(256, 2)
void flash_attn_tf32_kernel(const float* __restrict__ gq,
                            const float* __restrict__ gk,
                            const float* __restrict__ gv,
                            float* __restrict__ out)
{
    extern __shared__ uint32_t smu[];
    uint32_t* QPs = smu;            // Q / P / Ops (aliased)
    uint32_t* Ks  = smu + 8704;
    uint32_t* Vs  = smu + 8704 + 4608;

    const int qbase = blockIdx.x * 128;
    const int bh    = blockIdx.y;
    const int b     = bh >> 3;
    const int h     = bh & 7;
    const int tid   = threadIdx.x;
    const int lane  = tid & 31;
    const int w     = tid >> 5;
    const int g     = lane >> 2;
    const int tg    = lane & 3;
    const int qr    = w * 16;

    const size_t chan0 = ((size_t)b * CDIM + h * DH) * LPAD;
    const float* qg = gq + chan0;
    const float* kg = gk + chan0;
    const float* vg = gv + chan0;

    // ---- Q fill: QPs[d][q] stride 136, scaled, tf32 (rows are 16B-aligned) ----
    for (int t = tid; t < 64 * 32; t += 256) {
        const int d = t >> 5, s4 = t & 31;
        const float4 v = *(const float4*)&qg[(size_t)d * LPAD + qbase + s4 * 4];
        uint4 u;
        u.x = f2tf32(v.x * SCALE); u.y = f2tf32(v.y * SCALE);
        u.z = f2tf32(v.z * SCALE); u.w = f2tf32(v.w * SCALE);
        *(uint4*)&QPs[d * 136 + s4 * 4] = u;
    }
    __syncthreads();

    // ---- preload Q A-fragments (whole Dh=64) ----
    uint32_t aQ[8][4];
    #pragma unroll
    for (int ks = 0; ks < 8; ks++) {
        aQ[ks][0] = QPs[(8 * ks + tg)     * 136 + qr + g];
        aQ[ks][1] = QPs[(8 * ks + tg)     * 136 + qr + g + 8];
        aQ[ks][2] = QPs[(8 * ks + tg + 4) * 136 + qr + g];
        aQ[ks][3] = QPs[(8 * ks + tg + 4) * 136 + qr + g + 8];
    }

    float m0 = -1e30f, m1 = -1e30f, l0 = 0.f, l1 = 0.f;
    float o[8][4];
    #pragma unroll
    for (int ni = 0; ni < 8; ni++)
        #pragma unroll
        for (int r = 0; r < 4; r++) o[ni][r] = 0.f;

    for (int kt = 0; kt < 16; kt++) {
        const int kbase = kt * 64;
        __syncthreads();   // previous tile fully consumed; Q preload done (kt=0)

        // ---- K/V fill: Ks[d][k] stride 72, Vs[d][k] stride 68 (all vector) ----
        for (int t = tid; t < 64 * 16; t += 256) {
            const int d = t >> 4, s4 = t & 15;
            const float4 kv = *(const float4*)&kg[(size_t)d * LPAD + kbase + s4 * 4];
            const float4 vv = *(const float4*)&vg[(size_t)d * LPAD + kbase + s4 * 4];
            uint4 ku, vu;
            ku.x = f2tf32(kv.x); ku.y = f2tf32(kv.y);
            ku.z = f2tf32(kv.z); ku.w = f2tf32(kv.w);
            vu.x = f2tf32(vv.x); vu.y = f2tf32(vv.y);
            vu.z = f2tf32(vv.z); vu.w = f2tf32(vv.w);
            *(uint4*)&Ks[d * 72 + s4 * 4] = ku;
            *(uint4*)&Vs[d * 68 + s4 * 4] = vu;
        }
        __syncthreads();

        // ---- S = (scaled Q)^T K : c[ni][..] covers 16 q x 64 k ----
        float c[8][4];
        #pragma unroll
        for (int ni = 0; ni < 8; ni++)
            #pragma unroll
            for (int r = 0; r < 4; r++) c[ni][r] = 0.f;

        #pragma unroll
        for (int ks = 0; ks < 8; ks++) {
            #pragma unroll
            for (int ni = 0; ni < 8; ni++) {
                const uint32_t b0 = Ks[(8 * ks + tg)     * 72 + 8 * ni + g];
                const uint32_t b1 = Ks[(8 * ks + tg + 4) * 72 + 8 * ni + g];
                mma_tf32(c[ni], aQ[ks], b0, b1);
            }
        }

        // ---- mask invalid keys (last tile only; pad keys are zeros) ----
        if (kt == 15) {
            #pragma unroll
            for (int ni = 0; ni < 8; ni++) {
                const int col = ni * 8 + 2 * tg;
                if (kbase + col     >= LP) { c[ni][0] = -1e30f; c[ni][2] = -1e30f; }
                if (kbase + col + 1 >= LP) { c[ni][1] = -1e30f; c[ni][3] = -1e30f; }
            }
        }

        // ---- online softmax (rows g and g+8, reduce over quad lanes) ----
        float mx0 = -1e30f, mx1 = -1e30f;
        #pragma unroll
        for (int ni = 0; ni < 8; ni++) {
            mx0 = fmaxf(mx0, fmaxf(c[ni][0], c[ni][1]));
            mx1 = fmaxf(mx1, fmaxf(c[ni][2], c[ni][3]));
        }
        mx0 = fmaxf(mx0, __shfl_xor_sync(0xffffffffu, mx0, 1));
        mx0 = fmaxf(mx0, __shfl_xor_sync(0xffffffffu, mx0, 2));
        mx1 = fmaxf(mx1, __shfl_xor_sync(0xffffffffu, mx1, 1));
        mx1 = fmaxf(mx1, __shfl_xor_sync(0xffffffffu, mx1, 2));

        const float mn0 = fmaxf(m0, mx0);
        const float mn1 = fmaxf(m1, mx1);
        const float al0 = __expf(m0 - mn0);
        const float al1 = __expf(m1 - mn1);
        m0 = mn0; m1 = mn1;

        float s0 = 0.f, s1 = 0.f;
        #pragma unroll
        for (int ni = 0; ni < 8; ni++) {
            c[ni][0] = __expf(c[ni][0] - mn0);
            c[ni][1] = __expf(c[ni][1] - mn0);
            c[ni][2] = __expf(c[ni][2] - mn1);
            c[ni][3] = __expf(c[ni][3] - mn1);
            s0 += c[ni][0] + c[ni][1];
            s1 += c[ni][2] + c[ni][3];
        }
        s0 += __shfl_xor_sync(0xffffffffu, s0, 1);
        s0 += __shfl_xor_sync(0xffffffffu, s0, 2);
        s1 += __shfl_xor_sync(0xffffffffu, s1, 1);
        s1 += __shfl_xor_sync(0xffffffffu, s1, 2);
        l0 = l0 * al0 + s0;
        l1 = l1 * al1 + s1;

        #pragma unroll
        for (int ni = 0; ni < 8; ni++) {
            o[ni][0] *= al0; o[ni][1] *= al0;
            o[ni][2] *= al1; o[ni][3] *= al1;
        }

        // ---- write P (tf32) to per-warp-private rows of QPs (stride 68) ----
        uint32_t* Ps = QPs;
        #pragma unroll
        for (int ni = 0; ni < 8; ni++) {
            const int col = ni * 8 + 2 * tg;
            uint2 p0 = make_uint2(f2tf32(c[ni][0]), f2tf32(c[ni][1]));
            uint2 p1 = make_uint2(f2tf32(c[ni][2]), f2tf32(c[ni][3]));
            *(uint2*)&Ps[(qr + g)     * 68 + col] = p0;
            *(uint2*)&Ps[(qr + g + 8) * 68 + col] = p1;
        }
        __syncwarp();

        // ---- O += P V ----
        #pragma unroll
        for (int ks = 0; ks < 8; ks++) {
            uint32_t aP[4];
            aP[0] = Ps[(qr + g)     * 68 + 8 * ks + tg];
            aP[1] = Ps[(qr + g + 8) * 68 + 8 * ks + tg];
            aP[2] = Ps[(qr + g)     * 68 + 8 * ks + tg + 4];
            aP[3] = Ps[(qr + g + 8) * 68 + 8 * ks + tg + 4];
            #pragma unroll
            for (int ni = 0; ni < 8; ni++) {
                const uint32_t b0 = Vs[(8 * ni + g) * 68 + 8 * ks + tg];
                const uint32_t b1 = Vs[(8 * ni + g) * 68 + 8 * ks + tg + 4];
                mma_tf32(o[ni], aP, b0, b1);
            }
        }
    }

    // ---- epilogue: divide by l, transpose through smem, coalesced store ----
    __syncthreads();                 // everyone done with Ps/Ks/Vs
    const float il0 = 1.f / l0;
    const float il1 = 1.f / l1;
    float* Ops = (float*)QPs;        // [d=64][q=128] stride 132
    #pragma unroll
    for (int ni = 0; ni < 8; ni++) {
        const int d0 = ni * 8 + 2 * tg;
        Ops[d0 * 132 + qr + g]           = o[ni][0] * il0;
        Ops[(d0 + 1) * 132 + qr + g]     = o[ni][1] * il0;
        Ops[d0 * 132 + qr + g + 8]       = o[ni][2] * il1;
        Ops[(d0 + 1) * 132 + qr + g + 8] = o[ni][3] * il1;
    }
    __syncthreads();

    for (int t = tid; t < 64 * 128; t += 256) {
        const int d = t >> 7, q2 = t & 127;
        const int lq = qbase + q2;
        if (lq < LP)
            out[((size_t)b * CDIM + h * DH + d) * LP + lq] = Ops[d * 132 + q2];
    }
}

// ---------------------------------------------------------------------------
extern "C" void kernel_launch(void* const* d_in, const int* in_sizes, int n_in,
                              void* d_out, int out_size)
{
    const float* x  = (const float*)d_in[0];
    const float* w0 = (const float*)d_in[1];
    const float* b0 = (const float*)d_in[2];
    const float* w1 = (const float*)d_in[3];
    const float* b1 = (const float*)d_in[4];
    const float* w2 = (const float*)d_in[5];
    const float* b2 = (const float*)d_in[6];
    float* out = (float*)d_out;

    float *pq, *pk, *pv;
    cudaGetSymbolAddress((void**)&pq, g_q);
    cudaGetSymbolAddress((void**)&pk, g_k);
    cudaGetSymbolAddress((void**)&pv, g_v);

    dim3 cgrid(8, 4, BATCH * 3);
    conv_tf32_kernel<<<cgrid, 256>>>(x, w0, b0, w1, b1, w2, b2, pq, pk, pv);

    cudaFuncSetAttribute(flash_attn_tf32_kernel,
                         cudaFuncAttributeMaxDynamicSharedMemorySize,
                         ATTN_SMEM_BYTES);
    dim3 agrid(8, 128);
    flash_attn_tf32_kernel<<<agrid, 256, ATTN_SMEM_BYTES>>>(pq, pk, pv, out);
}